// round 17
// baseline (speedup 1.0000x reference)
#include <cuda_runtime.h>
#include <cstdint>
#include <cstddef>

#define BB 1024
#define FF 4096
#define DD 32
#define NT 4             // n-tiles of 8: n 0-31 embed (bias via FFMA on A-frags)
#define MTILES 8
#define KSPLITS 32
#define K_PER_CTA 128
#define KC 32
#define NCHUNK 4
#define A_STRIDE 132     // conflict-free, 16B aligned
#define B_STRIDE 40      // cols 0-31 embed, col 32 bias
#define NBP 36           // partials row stride (0-31 s, 32 bias); 36*4B keeps n-quads 16B-aligned
#define SMEM_FLOATS (128 * A_STRIDE + K_PER_CTA * B_STRIDE)   // 86 KB

// non-atomic split-K partials: [ksplit][row][n]
__device__ float g_part[(size_t)KSPLITS * BB * NBP];

__device__ __forceinline__ uint32_t smem_u32(const void* p) {
    uint32_t a;
    asm("{ .reg .u64 t; cvta.to.shared.u64 t, %1; cvt.u32.u64 %0, t; }" : "=r"(a) : "l"(p));
    return a;
}
__device__ __forceinline__ void cp16(uint32_t dst, const void* src) {
    asm volatile("cp.async.cg.shared.global [%0], [%1], 16;" :: "r"(dst), "l"(src));
}
__device__ __forceinline__ void cp4(uint32_t dst, const void* src) {
    asm volatile("cp.async.ca.shared.global [%0], [%1], 4;" :: "r"(dst), "l"(src));
}
__device__ __forceinline__ void cp_commit() { asm volatile("cp.async.commit_group;"); }
template <int N>
__device__ __forceinline__ void cp_wait() { asm volatile("cp.async.wait_group %0;" :: "n"(N)); }

// ---------------- GEMM: tf32 mma.sync (R15 config, proven), float2 epilogue ----------------
__global__ void __launch_bounds__(256, 2)
fm_gemm(const float* __restrict__ data,
        const float* __restrict__ embed,
        const float* __restrict__ bias)
{
    extern __shared__ float sm[];
    float* As = sm;                       // [row][k] stride 132
    float* Bs = sm + 128 * A_STRIDE;      // [k][n]  stride 40

    const int t = threadIdx.x;
    const int w = t >> 5, lane = t & 31;
    const int g = lane >> 2, ctg = lane & 3;
    const int mtile = blockIdx.x & 7;
    const int ksplit = blockIdx.x >> 3;
    const int kbase = ksplit * K_PER_CTA;
    const float* arow0 = data + (size_t)(mtile * 128) * FF + kbase;

    // issue ALL loads up front, one commit group per 32-k chunk
    #pragma unroll
    for (int c = 0; c < NCHUNK; c++) {
        #pragma unroll
        for (int i = 0; i < 4; i++) {
            const int idx = t + i * 256;
            const int row = idx >> 3, kq = (idx & 7) << 2;
            cp16(smem_u32(&As[row * A_STRIDE + c * KC + kq]),
                 arow0 + (size_t)row * FF + c * KC + kq);
        }
        const int k = t >> 3, q4 = (t & 7) << 2;
        cp16(smem_u32(&Bs[(c * KC + k) * B_STRIDE + q4]),
             embed + (size_t)(kbase + c * KC + k) * DD + q4);
        if (t < KC)
            cp4(smem_u32(&Bs[(c * KC + t) * B_STRIDE + 32]), bias + kbase + c * KC + t);
        cp_commit();
    }

    float acc[NT][4];
    #pragma unroll
    for (int nt = 0; nt < NT; nt++)
        #pragma unroll
        for (int j = 0; j < 4; j++) acc[nt][j] = 0.f;
    float bacc0 = 0.f, bacc1 = 0.f;

    const float* Aw = &As[(w * 16) * A_STRIDE];

    #pragma unroll
    for (int ch = 0; ch < NCHUNK; ch++) {
        if (ch == 0)      cp_wait<3>();
        else if (ch == 1) cp_wait<2>();
        else if (ch == 2) cp_wait<1>();
        else              cp_wait<0>();
        __syncthreads();

        #pragma unroll
        for (int ks = 0; ks < 4; ks++) {
            const int k0 = ch * KC + ks * 8;
            const uint32_t a0 = __float_as_uint(Aw[g * A_STRIDE + k0 + ctg]);
            const uint32_t a1 = __float_as_uint(Aw[(g + 8) * A_STRIDE + k0 + ctg]);
            const uint32_t a2 = __float_as_uint(Aw[g * A_STRIDE + k0 + ctg + 4]);
            const uint32_t a3 = __float_as_uint(Aw[(g + 8) * A_STRIDE + k0 + ctg + 4]);

            const float bk  = Bs[(k0 + ctg) * B_STRIDE + 32];
            const float bk4 = Bs[(k0 + ctg + 4) * B_STRIDE + 32];
            bacc0 = fmaf(__uint_as_float(a0), bk,  bacc0);
            bacc0 = fmaf(__uint_as_float(a2), bk4, bacc0);
            bacc1 = fmaf(__uint_as_float(a1), bk,  bacc1);
            bacc1 = fmaf(__uint_as_float(a3), bk4, bacc1);

            #pragma unroll
            for (int nt = 0; nt < NT; nt++) {
                const uint32_t b0 = __float_as_uint(Bs[(k0 + ctg) * B_STRIDE + nt * 8 + g]);
                const uint32_t b1 = __float_as_uint(Bs[(k0 + ctg + 4) * B_STRIDE + nt * 8 + g]);
                asm volatile(
                    "mma.sync.aligned.m16n8k8.row.col.f32.tf32.tf32.f32 "
                    "{%0,%1,%2,%3}, {%4,%5,%6,%7}, {%8,%9}, {%0,%1,%2,%3};"
                    : "+f"(acc[nt][0]), "+f"(acc[nt][1]), "+f"(acc[nt][2]), "+f"(acc[nt][3])
                    : "r"(a0), "r"(a1), "r"(a2), "r"(a3), "r"(b0), "r"(b1));
            }
        }
    }

    // epilogue: float2 stores into this ksplit's private slab
    float* pbase = g_part + (size_t)ksplit * BB * NBP;
    const int mbase = mtile * 128 + w * 16;
    #pragma unroll
    for (int nt = 0; nt < NT; nt++) {
        const int n0 = nt * 8 + 2 * ctg;                       // even -> 8B aligned
        const int m0 = mbase + g, m1 = mbase + g + 8;
        *reinterpret_cast<float2*>(&pbase[(size_t)m0 * NBP + n0]) =
            make_float2(acc[nt][0], acc[nt][1]);
        *reinterpret_cast<float2*>(&pbase[(size_t)m1 * NBP + n0]) =
            make_float2(acc[nt][2], acc[nt][3]);
    }
    bacc0 += __shfl_xor_sync(0xffffffffu, bacc0, 1);
    bacc0 += __shfl_xor_sync(0xffffffffu, bacc0, 2);
    bacc1 += __shfl_xor_sync(0xffffffffu, bacc1, 1);
    bacc1 += __shfl_xor_sync(0xffffffffu, bacc1, 2);
    if (ctg == 0) {
        pbase[(size_t)(mbase + g) * NBP + 32]     = bacc0;
        pbase[(size_t)(mbase + g + 8) * NBP + 32] = bacc1;
    }

    asm volatile("griddepcontrol.launch_dependents;");
}

// ---------------- finisher: vectorized (warp = 4 rows, LDG.128), sigmoid ----------------
__global__ void __launch_bounds__(64)
fm_finish(const float* __restrict__ gbias, float* __restrict__ out)
{
    asm volatile("griddepcontrol.wait;" ::: "memory");

    const int w = threadIdx.x >> 5, lane = threadIdx.x & 31;
    const int r = lane >> 3;             // row within warp group (0..3)
    const int q = lane & 7;              // n-quad (0..7) -> n = 4q..4q+3
    const int row = blockIdx.x * 8 + w * 4 + r;

    // sum partials over 32 ksplits: one LDG.128 per ksplit (16B-aligned: NBP=36, n0 mult of 4)
    float4 s4 = make_float4(0.f, 0.f, 0.f, 0.f);
    const float* base = g_part + (size_t)row * NBP + q * 4;
    #pragma unroll
    for (int k = 0; k < KSPLITS; k++) {
        const float4 v = *reinterpret_cast<const float4*>(base + (size_t)k * BB * NBP);
        s4.x += v.x; s4.y += v.y; s4.z += v.z; s4.w += v.w;
    }
    float v = s4.x * s4.x + s4.y * s4.y + s4.z * s4.z + s4.w * s4.w;

    // bias partials: lane q covers ksplits q, q+8, q+16, q+24
    const float* bb = g_part + (size_t)row * NBP + 32;
    #pragma unroll
    for (int k = 0; k < 4; k++)
        v += bb[(size_t)(q + k * 8) * BB * NBP];

    // reduce across the 8 lanes of this row (lanes r*8..r*8+7: xor 1,2,4 stay in group)
    v += __shfl_xor_sync(0xffffffffu, v, 1);
    v += __shfl_xor_sync(0xffffffffu, v, 2);
    v += __shfl_xor_sync(0xffffffffu, v, 4);

    if (q == 0)
        out[row] = 1.0f / (1.0f + __expf(-(gbias[0] + v)));
}

extern "C" void kernel_launch(void* const* d_in, const int* in_sizes, int n_in,
                              void* d_out, int out_size)
{
    const float* data  = (const float*)d_in[0];
    const float* embed = (const float*)d_in[1];
    const float* bias  = (const float*)d_in[2];
    const float* gb    = (const float*)d_in[3];
    float* out = (float*)d_out;

    const int smem_bytes = SMEM_FLOATS * (int)sizeof(float);
    cudaFuncSetAttribute(fm_gemm, cudaFuncAttributeMaxDynamicSharedMemorySize, smem_bytes);

    fm_gemm<<<MTILES * KSPLITS, 256, smem_bytes>>>(data, embed, bias);

    cudaLaunchConfig_t cfg = {};
    cfg.gridDim = dim3(BB / 8);
    cfg.blockDim = dim3(64);
    cfg.dynamicSmemBytes = 0;
    cfg.stream = 0;
    cudaLaunchAttribute attr[1];
    attr[0].id = cudaLaunchAttributeProgrammaticStreamSerialization;
    attr[0].val.programmaticStreamSerializationAllowed = 1;
    cfg.attrs = attr;
    cfg.numAttrs = 1;
    cudaLaunchKernelEx(&cfg, fm_finish, gb, out);
}